// round 2
// baseline (speedup 1.0000x reference)
#include <cuda_runtime.h>
#include <math.h>
#include <stdint.h>

// Batched FFT: B=8192 rows, N=4096, complex fp32 (separate re/im), out = [Yre; Yim].
//
// 4096 = 16*16*16 four-step decomposition (same math as round 1), now wrapped in a
// persistent-CTA, double-buffered cp.async.bulk pipeline:
//   - grid = 3 CTAs/SM, each CTA statically owns rows {bid, bid+G, ...}
//   - input rows prefetched 2 iterations ahead via cp.async.bulk -> smem + mbarrier
//   - exchange buffers alias the input staging region (barrier-separated)
//   - exch-1 row stride 258, exch-2 row stride 272: conflict-free banks on both
//     store and load phases (float arrays, re/im split).

#define NFFT 4096
#define TPB  256

#define BUF_FLOATS 8704        // per-buffer floats (34816 B)
#define IN_IM_OFF  4352        // input im offset (floats), 16B-aligned (17408 B)
#define E1_STRIDE  258         // exch-1 row stride (floats)
#define E1_IM_OFF  4128        // exch-1 im offset: 16*258 = 4128
#define E2_STRIDE  272         // exch-2 row stride (floats)
#define E2_IM_OFF  4352        // exch-2 im offset: 16*272 = 4352
#define SMEM_BYTES (2 * BUF_FLOATS * 4 + 16)   // 2 buffers + 2 mbarriers

__device__ __forceinline__ unsigned smem_u32(const void* p) {
    return (unsigned)__cvta_generic_to_shared(p);
}

__device__ __forceinline__ void mbar_init(unsigned mbar, unsigned count) {
    asm volatile("mbarrier.init.shared.b64 [%0], %1;" :: "r"(mbar), "r"(count) : "memory");
}

__device__ __forceinline__ void mbar_expect_tx(unsigned mbar, unsigned bytes) {
    asm volatile("mbarrier.arrive.expect_tx.shared.b64 _, [%0], %1;"
                 :: "r"(mbar), "r"(bytes) : "memory");
}

__device__ __forceinline__ void bulk_g2s(unsigned dst, const void* src,
                                         unsigned bytes, unsigned mbar) {
    asm volatile(
        "cp.async.bulk.shared::cluster.global.mbarrier::complete_tx::bytes "
        "[%0], [%1], %2, [%3];"
        :: "r"(dst), "l"(src), "r"(bytes), "r"(mbar) : "memory");
}

__device__ __forceinline__ void mbar_wait(unsigned mbar, unsigned phase) {
    asm volatile(
        "{\n\t.reg .pred P;\n"
        "WAIT_%=:\n\t"
        "mbarrier.try_wait.parity.acquire.cta.shared::cta.b64 P, [%0], %1;\n\t"
        "@!P bra WAIT_%=;\n\t}"
        :: "r"(mbar), "r"(phase) : "memory");
}

__device__ __forceinline__ float2 cmul(float2 a, float2 b) {
    return make_float2(fmaf(a.x, b.x, -a.y * b.y),
                       fmaf(a.x, b.y,  a.y * b.x));
}

__device__ __forceinline__ void dft4(float2 a, float2 b, float2 c, float2 d,
                                     float2& o0, float2& o1, float2& o2, float2& o3) {
    float2 s0 = make_float2(a.x + c.x, a.y + c.y);
    float2 s1 = make_float2(a.x - c.x, a.y - c.y);
    float2 s2 = make_float2(b.x + d.x, b.y + d.y);
    float2 s3 = make_float2(b.x - d.x, b.y - d.y);
    o0 = make_float2(s0.x + s2.x, s0.y + s2.y);
    o2 = make_float2(s0.x - s2.x, s0.y - s2.y);
    o1 = make_float2(s1.x + s3.y, s1.y - s3.x);   // s1 - i*s3
    o3 = make_float2(s1.x - s3.y, s1.y + s3.x);   // s1 + i*s3
}

// 16-point forward DFT, natural in -> natural out (radix-4 x radix-4).
__device__ __forceinline__ void fft16(float2 v[16]) {
    const float C1 = 0.92387953251128675613f;
    const float S1 = 0.38268343236508977173f;
    const float R  = 0.70710678118654752440f;

    float2 a[4][4];
#pragma unroll
    for (int l = 0; l < 4; l++)
        dft4(v[l], v[l + 4], v[l + 8], v[l + 12],
             a[l][0], a[l][1], a[l][2], a[l][3]);

    a[1][1] = cmul(a[1][1], make_float2( C1, -S1));
    a[1][2] = cmul(a[1][2], make_float2(  R,  -R));
    a[1][3] = cmul(a[1][3], make_float2( S1, -C1));
    a[2][1] = cmul(a[2][1], make_float2(  R,  -R));
    { float2 x = a[2][2]; a[2][2] = make_float2(x.y, -x.x); }
    a[2][3] = cmul(a[2][3], make_float2( -R,  -R));
    a[3][1] = cmul(a[3][1], make_float2( S1, -C1));
    a[3][2] = cmul(a[3][2], make_float2( -R,  -R));
    a[3][3] = cmul(a[3][3], make_float2(-C1,  S1));

#pragma unroll
    for (int p = 0; p < 4; p++)
        dft4(a[0][p], a[1][p], a[2][p], a[3][p],
             v[p], v[4 + p], v[8 + p], v[12 + p]);
}

__global__ void __launch_bounds__(TPB, 3)
fft4096_persistent(const float* __restrict__ xre,
                   const float* __restrict__ xim,
                   float* __restrict__ out,
                   int batch) {
    extern __shared__ float smem[];
    float* buf[2] = { smem, smem + BUF_FLOATS };
    unsigned mbar[2];
    {
        unsigned mb = smem_u32(smem + 2 * BUF_FLOATS);
        mbar[0] = mb;
        mbar[1] = mb + 8;
    }

    const int t   = threadIdx.x;
    const int bid = blockIdx.x;
    const int G   = gridDim.x;

    // hoisted base twiddles (depend only on t)
    float s1w, c1w, s2w, c2w;
    sincosf(-6.2831853071795864769f * (float)t / 4096.0f, &s1w, &c1w);
    sincosf(-6.2831853071795864769f * (float)(t >> 4) / 256.0f, &s2w, &c2w);
    const float2 w1 = make_float2(c1w, s1w);
    const float2 w2 = make_float2(c2w, s2w);
    const int k1 = t & 15;
    const int hi = t >> 4;   // p2 in pass 2, q1 in pass 3

    if (t == 0) {
        mbar_init(mbar[0], 1);
        mbar_init(mbar[1], 1);
        // prologue prefetch: rows bid and bid+G
        int r0 = bid;
        if (r0 < batch) {
            mbar_expect_tx(mbar[0], 32768);
            bulk_g2s(smem_u32(buf[0]),             xre + (size_t)r0 * NFFT, 16384, mbar[0]);
            bulk_g2s(smem_u32(buf[0] + IN_IM_OFF), xim + (size_t)r0 * NFFT, 16384, mbar[0]);
        }
        int r1 = bid + G;
        if (r1 < batch) {
            mbar_expect_tx(mbar[1], 32768);
            bulk_g2s(smem_u32(buf[1]),             xre + (size_t)r1 * NFFT, 16384, mbar[1]);
            bulk_g2s(smem_u32(buf[1] + IN_IM_OFF), xim + (size_t)r1 * NFFT, 16384, mbar[1]);
        }
    }
    __syncthreads();

    int j = 0;
    for (int row = bid; row < batch; row += G, ++j) {
        const int cur = j & 1;
        float* bf = buf[cur];
        mbar_wait(mbar[cur], (j >> 1) & 1);

        float2 v[16];
#pragma unroll
        for (int n1 = 0; n1 < 16; n1++)
            v[n1] = make_float2(bf[n1 * 256 + t], bf[IN_IM_OFF + n1 * 256 + t]);

        // ---- pass 1: DFT16 over n1, thread t = n2 ----
        fft16(v);
        {
            float2 wk = w1;
#pragma unroll
            for (int k = 1; k < 16; k++) {
                v[k] = cmul(v[k], wk);
                wk = cmul(wk, w1);
            }
        }

        __syncthreads();   // pass-1 input reads done; exch-1 may overwrite

        // ---- exchange 1 (stride 258, re/im split) ----
#pragma unroll
        for (int k = 0; k < 16; k++) {
            bf[k * E1_STRIDE + t]             = v[k].x;
            bf[E1_IM_OFF + k * E1_STRIDE + t] = v[k].y;
        }
        __syncthreads();
#pragma unroll
        for (int p1 = 0; p1 < 16; p1++) {
            int idx = k1 * E1_STRIDE + p1 * 16 + hi;
            v[p1] = make_float2(bf[idx], bf[E1_IM_OFF + idx]);
        }

        // ---- pass 2: DFT16 over p1 ----
        fft16(v);
        {
            float2 wk = w2;
#pragma unroll
            for (int q = 1; q < 16; q++) {
                v[q] = cmul(v[q], wk);
                wk = cmul(wk, w2);
            }
        }

        __syncthreads();   // exch-1 reads done; exch-2 may overwrite

        // ---- exchange 2 (stride 272) ----
#pragma unroll
        for (int q = 0; q < 16; q++) {
            bf[q * E2_STRIDE + t]             = v[q].x;
            bf[E2_IM_OFF + q * E2_STRIDE + t] = v[q].y;
        }
        __syncthreads();
#pragma unroll
        for (int p2 = 0; p2 < 16; p2++) {
            int idx = hi * E2_STRIDE + p2 * 16 + k1;
            v[p2] = make_float2(bf[idx], bf[E2_IM_OFF + idx]);
        }

        __syncthreads();   // all smem reads of this buffer done

        // prefetch row j+2 into this buffer, overlapping pass-3 compute + stores
        if (t == 0) {
            int nr = row + 2 * G;
            if (nr < batch) {
                mbar_expect_tx(mbar[cur], 32768);
                bulk_g2s(smem_u32(bf),             xre + (size_t)nr * NFFT, 16384, mbar[cur]);
                bulk_g2s(smem_u32(bf + IN_IM_OFF), xim + (size_t)nr * NFFT, 16384, mbar[cur]);
            }
        }

        // ---- pass 3: DFT16 over p2; Y[q2*256 + t] ----
        fft16(v);

        float* outre = out + (size_t)row * NFFT;
        float* outim = out + (size_t)batch * NFFT + (size_t)row * NFFT;
#pragma unroll
        for (int q2 = 0; q2 < 16; q2++) {
            outre[q2 * 256 + t] = v[q2].x;
            outim[q2 * 256 + t] = v[q2].y;
        }
    }
}

extern "C" void kernel_launch(void* const* d_in, const int* in_sizes, int n_in,
                              void* d_out, int out_size) {
    const float* xre = (const float*)d_in[0];
    const float* xim = (const float*)d_in[1];
    float* out = (float*)d_out;
    const int batch = in_sizes[0] / NFFT;

    int sms = 0;
    cudaDeviceGetAttribute(&sms, cudaDevAttrMultiProcessorCount, 0);
    if (sms <= 0) sms = 148;
    int grid = sms * 3;
    if (grid > batch) grid = batch;

    cudaFuncSetAttribute(fft4096_persistent,
                         cudaFuncAttributeMaxDynamicSharedMemorySize, SMEM_BYTES);
    fft4096_persistent<<<grid, TPB, SMEM_BYTES>>>(xre, xim, out, batch);
}

// round 3
// speedup vs baseline: 1.0719x; 1.0719x over previous
#include <cuda_runtime.h>
#include <math.h>

// Batched FFT: B=8192 rows, N=4096, complex fp32 (separate re/im), out = [Yre; Yim].
//
// Radix-8^4 decomposition, 512 threads/CTA, 8 complex points/thread, one row/CTA.
//   n = n1*512 + n2;  n2 = m1*64 + m2;  m2 = r1*8 + r2
//   k = h*512 + i1*64 + j1*8 + k1
// Pass 1 (thread t=n2):            B[k1] = DFT8_{n1}(x[n1*512+t]) * W4096^{t*k1}
// Exch 1, pass 2 (t=(k1,m2)):      C[j1] = DFT8_{m1}(B) * W512^{m2*j1}
// Exch 2, pass 3 (t=(k1,j1,r2)):   D[i1] = DFT8_{r1}(C) * W64^{r2*i1}
// Exch 3, pass 4 (t=(i1,j1,k1)):   E[h]  = DFT8_{r2}(D);  Y[h*512 + t] = E[h]
//
// All global accesses coalesced. All smem exchange phases bank-conflict-free:
//   addr = k1*577 + j1*72 + i1*9 + r2   (577 odd, 72==8 mod 32, 9 odd)
// Occupancy target: 3 CTAs/SM x 16 warps = 48 warps (launch_bounds caps regs at 42).

#define NFFT 4096
#define TPB  512
#define BUFSZ 4616   // per-component smem floats (max addr 4613)

__device__ __forceinline__ float2 cmul(float2 a, float2 b) {
    return make_float2(fmaf(a.x, b.x, -a.y * b.y),
                       fmaf(a.x, b.y,  a.y * b.x));
}

__device__ __forceinline__ void dft4(float2 a, float2 b, float2 c, float2 d,
                                     float2& o0, float2& o1, float2& o2, float2& o3) {
    // forward DFT4 (W4 = -i)
    float2 s0 = make_float2(a.x + c.x, a.y + c.y);
    float2 s1 = make_float2(a.x - c.x, a.y - c.y);
    float2 s2 = make_float2(b.x + d.x, b.y + d.y);
    float2 s3 = make_float2(b.x - d.x, b.y - d.y);
    o0 = make_float2(s0.x + s2.x, s0.y + s2.y);
    o2 = make_float2(s0.x - s2.x, s0.y - s2.y);
    o1 = make_float2(s1.x + s3.y, s1.y - s3.x);   // s1 - i*s3
    o3 = make_float2(s1.x - s3.y, s1.y + s3.x);   // s1 + i*s3
}

// 8-point forward DFT, natural in -> natural out (split-radix-2 over DFT4).
__device__ __forceinline__ void dft8(float2 v[8]) {
    const float R = 0.70710678118654752440f;
    float2 e0, e1, e2, e3, o0, o1, o2, o3;
    dft4(v[0], v[2], v[4], v[6], e0, e1, e2, e3);
    dft4(v[1], v[3], v[5], v[7], o0, o1, o2, o3);
    // o_k *= W8^k : W8^1=(R,-R), W8^2=-i, W8^3=(-R,-R)
    o1 = cmul(o1, make_float2( R, -R));
    { float2 x = o2; o2 = make_float2(x.y, -x.x); }
    o3 = cmul(o3, make_float2(-R, -R));
    v[0] = make_float2(e0.x + o0.x, e0.y + o0.y);
    v[4] = make_float2(e0.x - o0.x, e0.y - o0.y);
    v[1] = make_float2(e1.x + o1.x, e1.y + o1.y);
    v[5] = make_float2(e1.x - o1.x, e1.y - o1.y);
    v[2] = make_float2(e2.x + o2.x, e2.y + o2.y);
    v[6] = make_float2(e2.x - o2.x, e2.y - o2.y);
    v[3] = make_float2(e3.x + o3.x, e3.y + o3.y);
    v[7] = make_float2(e3.x - o3.x, e3.y - o3.y);
}

// twiddle v[k] *= w^k for k=1..7 via recurrence
__device__ __forceinline__ void twiddle8(float2 v[8], float ang) {
    float s, c;
    sincosf(ang, &s, &c);
    float2 w  = make_float2(c, s);
    float2 wk = w;
#pragma unroll
    for (int k = 1; k < 8; k++) {
        v[k] = cmul(v[k], wk);
        wk = cmul(wk, w);
    }
}

__global__ void __launch_bounds__(TPB, 3)
fft4096_r8(const float* __restrict__ xre,
           const float* __restrict__ xim,
           float* __restrict__ out,
           int batch) {
    __shared__ float shre[BUFSZ];
    __shared__ float shim[BUFSZ];

    const int b = blockIdx.x;
    const int t = threadIdx.x;

    const float* xr = xre + (size_t)b * NFFT;
    const float* xi = xim + (size_t)b * NFFT;

    float2 v[8];
#pragma unroll
    for (int n1 = 0; n1 < 8; n1++)
        v[n1] = make_float2(xr[n1 * 512 + t], xi[n1 * 512 + t]);

    // ---- pass 1: DFT8 over n1, twiddle W4096^{t*k1} ----
    dft8(v);
    twiddle8(v, -6.2831853071795864769f * (float)t / 4096.0f);

    // ---- exchange 1: sh[k1*512 + n2] ----
#pragma unroll
    for (int k1 = 0; k1 < 8; k1++) {
        shre[k1 * 512 + t] = v[k1].x;
        shim[k1 * 512 + t] = v[k1].y;
    }
    __syncthreads();
    {
        const int k1 = t >> 6;
        const int m2 = t & 63;
        const int base = k1 * 512 + m2;
#pragma unroll
        for (int m1 = 0; m1 < 8; m1++) {
            int idx = base + m1 * 64;
            v[m1] = make_float2(shre[idx], shim[idx]);
        }

        // ---- pass 2: DFT8 over m1, twiddle W512^{m2*j1} ----
        dft8(v);
        twiddle8(v, -6.2831853071795864769f * (float)m2 / 512.0f);

        __syncthreads();

        // ---- exchange 2: sh[k1*577 + j1*72 + m2] ----
        const int base2 = k1 * 577 + m2;
#pragma unroll
        for (int j1 = 0; j1 < 8; j1++) {
            shre[base2 + j1 * 72] = v[j1].x;
            shim[base2 + j1 * 72] = v[j1].y;
        }
    }
    __syncthreads();
    {
        const int k1 = t >> 6;
        const int j1 = (t >> 3) & 7;
        const int r2 = t & 7;
        const int base = k1 * 577 + j1 * 72 + r2;
#pragma unroll
        for (int r1 = 0; r1 < 8; r1++) {
            int idx = base + r1 * 8;
            v[r1] = make_float2(shre[idx], shim[idx]);
        }

        // ---- pass 3: DFT8 over r1, twiddle W64^{r2*i1} ----
        dft8(v);
        twiddle8(v, -6.2831853071795864769f * (float)r2 / 64.0f);

        __syncthreads();

        // ---- exchange 3: sh[k1*577 + j1*72 + i1*9 + r2] ----
#pragma unroll
        for (int i1 = 0; i1 < 8; i1++) {
            shre[base + i1 * 9] = v[i1].x;   // base = k1*577 + j1*72 + r2
            shim[base + i1 * 9] = v[i1].y;
        }
    }
    __syncthreads();
    {
        // pass-4 thread remap: u = i1*64 + j1*8 + k1 (keeps output coalesced)
        const int i1 = t >> 6;
        const int j1 = (t >> 3) & 7;
        const int k1 = t & 7;
        const int base = k1 * 577 + j1 * 72 + i1 * 9;
#pragma unroll
        for (int r2 = 0; r2 < 8; r2++)
            v[r2] = make_float2(shre[base + r2], shim[base + r2]);
    }

    // ---- pass 4: DFT8 over r2 -> h;  Y[h*512 + t] ----
    dft8(v);

    float* outre = out + (size_t)b * NFFT;
    float* outim = out + (size_t)batch * NFFT + (size_t)b * NFFT;
#pragma unroll
    for (int h = 0; h < 8; h++) {
        outre[h * 512 + t] = v[h].x;
        outim[h * 512 + t] = v[h].y;
    }
}

extern "C" void kernel_launch(void* const* d_in, const int* in_sizes, int n_in,
                              void* d_out, int out_size) {
    const float* xre = (const float*)d_in[0];
    const float* xim = (const float*)d_in[1];
    float* out = (float*)d_out;
    const int batch = in_sizes[0] / NFFT;

    fft4096_r8<<<batch, TPB>>>(xre, xim, out, batch);
}